// round 1
// baseline (speedup 1.0000x reference)
#include <cuda_runtime.h>
#include <cuda_bf16.h>

// Problem constants
#define BB 8
#define TT 2048
#define CC 1024
#define HH 64
#define BT (BB * TT)          // 16384 rows
#define NSPLIT 4
#define SPLIT_LEN (TT / NSPLIT)  // 512

// Scratch (device globals: allocation-free rule)
__device__ float g_q[BT * HH];
__device__ float g_k[BT * HH];
__device__ float g_v[BT * HH];
__device__ float g_pm[NSPLIT * BT];
__device__ float g_pl[NSPLIT * BT];
__device__ float g_po[NSPLIT * BT * HH];

// ---------------------------------------------------------------------------
// Kernel 1: QKV projection. C = x @ W for W in {Wk, Wq, Wv} (blockIdx.y picks).
// M=16384, N=64, K=1024.  Block tile 64x64, K-tile 16, 128 threads, 8x4 micro.
// ---------------------------------------------------------------------------
__global__ __launch_bounds__(128) void qkv_kernel(
    const float* __restrict__ x,
    const float* __restrict__ Wk,
    const float* __restrict__ Wq,
    const float* __restrict__ Wv)
{
    __shared__ float sa[16][68];  // [k][m], padded
    __shared__ float sb[16][64];  // [k][n]

    const float* W = (blockIdx.y == 0) ? Wk : (blockIdx.y == 1) ? Wq : Wv;
    float* out = (blockIdx.y == 0) ? g_k : (blockIdx.y == 1) ? g_q : g_v;

    const int m0 = blockIdx.x * 64;
    const int tid = threadIdx.x;
    const int tm = tid >> 4;   // 0..7  (owns 8 rows: tm*8 .. tm*8+7)
    const int tn = tid & 15;   // 0..15 (owns 4 cols: tn*4 .. tn*4+3)

    float acc[8][4];
#pragma unroll
    for (int i = 0; i < 8; i++)
#pragma unroll
        for (int j = 0; j < 4; j++) acc[i][j] = 0.f;

    for (int k0 = 0; k0 < CC; k0 += 16) {
        // Load A tile (64 rows x 16 k) transposed into sa[k][m]
#pragma unroll
        for (int i = 0; i < 2; i++) {
            int f = tid + i * 128;         // 0..255 float4s
            int row = f >> 2;              // 0..63
            int kq = (f & 3) * 4;          // 0,4,8,12
            float4 v = *(const float4*)&x[(size_t)(m0 + row) * CC + k0 + kq];
            sa[kq + 0][row] = v.x;
            sa[kq + 1][row] = v.y;
            sa[kq + 2][row] = v.z;
            sa[kq + 3][row] = v.w;
        }
        // Load B tile (16 k x 64 n)
#pragma unroll
        for (int i = 0; i < 2; i++) {
            int f = tid + i * 128;         // 0..255 float4s
            int row = f >> 4;              // 0..15
            int nq = (f & 15) * 4;         // 0..60
            *(float4*)&sb[row][nq] = *(const float4*)&W[(size_t)(k0 + row) * HH + nq];
        }
        __syncthreads();

#pragma unroll
        for (int k = 0; k < 16; k++) {
            float4 a0 = *(const float4*)&sa[k][tm * 8];
            float4 a1 = *(const float4*)&sa[k][tm * 8 + 4];
            float4 b  = *(const float4*)&sb[k][tn * 4];
            float av[8] = {a0.x, a0.y, a0.z, a0.w, a1.x, a1.y, a1.z, a1.w};
            float bv[4] = {b.x, b.y, b.z, b.w};
#pragma unroll
            for (int i = 0; i < 8; i++)
#pragma unroll
                for (int j = 0; j < 4; j++)
                    acc[i][j] += av[i] * bv[j];
        }
        __syncthreads();
    }

#pragma unroll
    for (int i = 0; i < 8; i++) {
        float4 v = make_float4(acc[i][0], acc[i][1], acc[i][2], acc[i][3]);
        *(float4*)&out[(size_t)(m0 + tm * 8 + i) * HH + tn * 4] = v;
    }
}

// ---------------------------------------------------------------------------
// Kernel 2: flash attention (causal), split over key range into NSPLIT chunks.
// Grid (T/128, B, NSPLIT). 128 threads; thread = one query row.
// q[64], o[64] held in registers; K/V tiles (64x64) in smem (warp-broadcast).
// ---------------------------------------------------------------------------
__global__ __launch_bounds__(128, 1) void attn_kernel()
{
    const int qtile = blockIdx.x;
    const int b = blockIdx.y;
    const int split = blockIdx.z;
    const int tid = threadIdx.x;

    const int t = qtile * 128 + tid;        // this thread's query row
    const int tmax = qtile * 128 + 127;     // max row in block
    const int ks0 = split * SPLIT_LEN;
    const int ks1 = min((split + 1) * SPLIT_LEN, tmax + 1);  // multiple of 64

    __shared__ float sk[64][64];
    __shared__ float sv[64][64];

    // Load my q row into registers
    float q[HH];
    {
        const float* qr = g_q + (size_t)(b * TT + t) * HH;
#pragma unroll
        for (int h4 = 0; h4 < 16; h4++) {
            float4 v = *(const float4*)&qr[h4 * 4];
            q[h4 * 4 + 0] = v.x; q[h4 * 4 + 1] = v.y;
            q[h4 * 4 + 2] = v.z; q[h4 * 4 + 3] = v.w;
        }
    }

    float o[HH];
#pragma unroll
    for (int h = 0; h < HH; h++) o[h] = 0.f;
    float m = -1e30f;
    float l = 0.f;

    const float scale = 0.125f;  // 1/sqrt(64)

    for (int s0 = ks0; s0 < ks1; s0 += 64) {
        __syncthreads();
        // Load 64x64 K and V tiles (each thread: 8 float4 per tile)
#pragma unroll
        for (int i = 0; i < 8; i++) {
            int f = tid + i * 128;          // 0..1023 float4s
            int row = f >> 4;               // 0..63
            int c4 = (f & 15) * 4;          // 0..60
            *(float4*)&sk[row][c4] = *(const float4*)&g_k[(size_t)(b * TT + s0 + row) * HH + c4];
            *(float4*)&sv[row][c4] = *(const float4*)&g_v[(size_t)(b * TT + s0 + row) * HH + c4];
        }
        __syncthreads();

        const int send = min(ks1, t + 1) - s0;  // active keys for this thread

        for (int s = 0; s < 64; s++) {
            if (s < send) {
                // score = q . k[s]   (8 independent accumulation chains)
                float4 accA = make_float4(0.f, 0.f, 0.f, 0.f);
                float4 accB = make_float4(0.f, 0.f, 0.f, 0.f);
#pragma unroll
                for (int h4 = 0; h4 < 16; h4 += 2) {
                    float4 k0v = *(const float4*)&sk[s][h4 * 4];
                    float4 k1v = *(const float4*)&sk[s][h4 * 4 + 4];
                    accA.x += q[h4 * 4 + 0] * k0v.x;
                    accA.y += q[h4 * 4 + 1] * k0v.y;
                    accA.z += q[h4 * 4 + 2] * k0v.z;
                    accA.w += q[h4 * 4 + 3] * k0v.w;
                    accB.x += q[h4 * 4 + 4] * k1v.x;
                    accB.y += q[h4 * 4 + 5] * k1v.y;
                    accB.z += q[h4 * 4 + 6] * k1v.z;
                    accB.w += q[h4 * 4 + 7] * k1v.w;
                }
                float sc = ((accA.x + accA.y) + (accA.z + accA.w)) +
                           ((accB.x + accB.y) + (accB.z + accB.w));
                sc *= scale;

                if (sc > m) {
                    float corr = __expf(m - sc);
                    m = sc;
                    l *= corr;
#pragma unroll
                    for (int h = 0; h < HH; h++) o[h] *= corr;
                }
                float p = __expf(sc - m);
                l += p;
#pragma unroll
                for (int h4 = 0; h4 < 16; h4++) {
                    float4 vv = *(const float4*)&sv[s][h4 * 4];
                    o[h4 * 4 + 0] += p * vv.x;
                    o[h4 * 4 + 1] += p * vv.y;
                    o[h4 * 4 + 2] += p * vv.z;
                    o[h4 * 4 + 3] += p * vv.w;
                }
            }
        }
    }

    // Write partials
    const int row = b * TT + t;
    g_pm[split * BT + row] = m;
    g_pl[split * BT + row] = l;
    float* po = g_po + ((size_t)split * BT + row) * HH;
#pragma unroll
    for (int h4 = 0; h4 < 16; h4++) {
        float4 v = make_float4(o[h4 * 4 + 0], o[h4 * 4 + 1],
                               o[h4 * 4 + 2], o[h4 * 4 + 3]);
        *(float4*)&po[h4 * 4] = v;
    }
}

// ---------------------------------------------------------------------------
// Kernel 3: combine partials. Grid = BT blocks, 64 threads (h).
// ---------------------------------------------------------------------------
__global__ __launch_bounds__(64) void combine_kernel(float* __restrict__ out)
{
    const int row = blockIdx.x;
    const int h = threadIdx.x;

    float mv[NSPLIT];
    float lv[NSPLIT];
#pragma unroll
    for (int i = 0; i < NSPLIT; i++) {
        mv[i] = g_pm[i * BT + row];
        lv[i] = g_pl[i * BT + row];
    }
    float M = mv[0];
#pragma unroll
    for (int i = 1; i < NSPLIT; i++) M = fmaxf(M, mv[i]);

    float L = 0.f;
    float acc = 0.f;
#pragma unroll
    for (int i = 0; i < NSPLIT; i++) {
        float w = __expf(mv[i] - M);
        L += lv[i] * w;
        acc += g_po[((size_t)i * BT + row) * HH + h] * w;
    }
    out[(size_t)row * HH + h] = acc / L;
}

// ---------------------------------------------------------------------------
extern "C" void kernel_launch(void* const* d_in, const int* in_sizes, int n_in,
                              void* d_out, int out_size)
{
    const float* x  = (const float*)d_in[0];
    const float* Wk = (const float*)d_in[1];
    const float* Wq = (const float*)d_in[2];
    const float* Wv = (const float*)d_in[3];
    float* out = (float*)d_out;

    qkv_kernel<<<dim3(BT / 64, 3), 128>>>(x, Wk, Wq, Wv);
    attn_kernel<<<dim3(TT / 128, BB, NSPLIT), 128>>>();
    combine_kernel<<<dim3(BT), 64>>>(out);
}

// round 4
// speedup vs baseline: 1.0581x; 1.0581x over previous
#include <cuda_runtime.h>
#include <cuda_bf16.h>
#include <cstdint>

// Problem constants
#define BB 8
#define TT 2048
#define CC 1024
#define HH 64
#define BT (BB * TT)             // 16384 rows
#define NSPLIT 4
#define SPLIT_LEN (TT / NSPLIT)  // 512

// Scratch (device globals: allocation-free rule)
__device__ float g_q[BT * HH];
__device__ float g_k[BT * HH];
__device__ float g_v[BT * HH];
__device__ float g_pm[NSPLIT * BT];
__device__ float g_pl[NSPLIT * BT];
__device__ float g_po[NSPLIT * BT * HH];
// W split into bf16 hi/lo, transposed to [w][n][k] (K-major rows of 1024)
__device__ __align__(16) __nv_bfloat16 g_whi[3 * HH * CC];
__device__ __align__(16) __nv_bfloat16 g_wlo[3 * HH * CC];

// ---------------------------------------------------------------------------
// mma.sync / ldmatrix helpers (sm_80+, valid on sm_100 plain target)
// ---------------------------------------------------------------------------
__device__ __forceinline__ uint32_t smem_u32(const void* p) {
    uint32_t a;
    asm("{ .reg .u64 t; cvta.to.shared.u64 t, %1; cvt.u32.u64 %0, t; }"
        : "=r"(a) : "l"(p));
    return a;
}

__device__ __forceinline__ void ldsm4(uint32_t* r, uint32_t addr) {
    asm volatile("ldmatrix.sync.aligned.m8n8.x4.shared.b16 {%0,%1,%2,%3}, [%4];"
                 : "=r"(r[0]), "=r"(r[1]), "=r"(r[2]), "=r"(r[3]) : "r"(addr));
}

__device__ __forceinline__ void mma16816(float* c, const uint32_t* a,
                                         uint32_t b0, uint32_t b1) {
    asm volatile(
        "mma.sync.aligned.m16n8k16.row.col.f32.bf16.bf16.f32 "
        "{%0,%1,%2,%3}, {%4,%5,%6,%7}, {%8,%9}, {%0,%1,%2,%3};"
        : "+f"(c[0]), "+f"(c[1]), "+f"(c[2]), "+f"(c[3])
        : "r"(a[0]), "r"(a[1]), "r"(a[2]), "r"(a[3]), "r"(b0), "r"(b1));
}

// ---------------------------------------------------------------------------
// Kernel 0: split W into bf16 hi/lo, transposed to [w][n][k]
// ---------------------------------------------------------------------------
__global__ __launch_bounds__(256) void prep_w_kernel(
    const float* __restrict__ Wk, const float* __restrict__ Wq,
    const float* __restrict__ Wv)
{
    int i = blockIdx.x * 256 + threadIdx.x;   // over 3*64*1024
    int w = i >> 16;
    int rem = i & 65535;
    int n = rem >> 10;
    int k = rem & 1023;
    const float* W = (w == 0) ? Wk : (w == 1) ? Wq : Wv;
    float v = W[k * HH + n];
    __nv_bfloat16 h = __float2bfloat16(v);
    float r = v - __bfloat162float(h);
    g_whi[i] = h;
    g_wlo[i] = __float2bfloat16(r);
}

// ---------------------------------------------------------------------------
// Kernel 1: QKV projection via mma.sync (bf16 split precision, fp32 accum).
// CTA: 128 rows x (3 outputs x 64 cols). 8 warps; warp owns 16 rows x 64 x 3W.
// K-chunk 32 (2 mma k-steps), double-buffered smem, register prefetch.
// ---------------------------------------------------------------------------
#define KC 32
#define NCHUNK (CC / KC)        // 32
#define A_HI 0
#define A_LO 8192
#define B_HI 16384              // + w*4096
#define B_LO 28672              // + w*4096
#define STAGE 40960
#define QKV_SMEM (2 * STAGE)

__global__ __launch_bounds__(256, 1) void qkv_mma_kernel(const float* __restrict__ x)
{
    extern __shared__ __align__(16) char sm[];
    const uint32_t sbase = smem_u32(sm);

    const int tid = threadIdx.x;
    const int wid = tid >> 5;
    const int lane = tid & 31;
    const int m0 = blockIdx.x * 128;

    // ldmatrix lane-address components (byte offsets within a stage)
    const uint32_t aoff = (uint32_t)((wid * 16 + (lane & 15)) * 64 + ((lane >> 4) * 16));
    const uint32_t boff = (uint32_t)(((lane & 7) + ((lane >> 4) << 3)) * 64 +
                                     (((lane >> 3) & 1) * 16));

    float acc[3][8][4];
#pragma unroll
    for (int w = 0; w < 3; w++)
#pragma unroll
        for (int nt = 0; nt < 8; nt++)
#pragma unroll
            for (int j = 0; j < 4; j++) acc[w][nt][j] = 0.f;

    float4 xr[4];
    uint4 wr[6];

    // ---- prefetch chunk 0 ----
    {
        const int k0 = 0;
#pragma unroll
        for (int it = 0; it < 4; it++) {
            int f = tid + it * 256;          // 1024 float4: row*8 + q4
            int row = f >> 3, q4 = f & 7;
            xr[it] = *(const float4*)&x[(size_t)(m0 + row) * CC + k0 + q4 * 4];
        }
        const uint4* whi = (const uint4*)g_whi;
        const uint4* wlo = (const uint4*)g_wlo;
#pragma unroll
        for (int it = 0; it < 6; it++) {
            int u = tid + it * 256;          // 1536: first 768 hi, then lo
            int v = (u < 768) ? u : (u - 768);
            int w = v >> 8, n = (v & 255) >> 2, q = v & 3;
            uint32_t src = (uint32_t)(w * (HH * CC) + n * CC + k0) / 8 + q;
            wr[it] = (u < 768) ? whi[src] : wlo[src];
        }
    }

    for (int c = 0; c < NCHUNK; c++) {
        const int buf = c & 1;
        char* st = sm + buf * STAGE;
        const uint32_t stb = sbase + buf * STAGE;

        // ---- store prefetched chunk into smem (convert x to hi/lo) ----
#pragma unroll
        for (int it = 0; it < 4; it++) {
            int f = tid + it * 256;
            int row = f >> 3, q4 = f & 7;
            float4 v = xr[it];
            __nv_bfloat16 h0 = __float2bfloat16(v.x);
            __nv_bfloat16 h1 = __float2bfloat16(v.y);
            __nv_bfloat16 h2 = __float2bfloat16(v.z);
            __nv_bfloat16 h3 = __float2bfloat16(v.w);
            __nv_bfloat16 l0 = __float2bfloat16(v.x - __bfloat162float(h0));
            __nv_bfloat16 l1 = __float2bfloat16(v.y - __bfloat162float(h1));
            __nv_bfloat16 l2 = __float2bfloat16(v.z - __bfloat162float(h2));
            __nv_bfloat16 l3 = __float2bfloat16(v.w - __bfloat162float(h3));
            uint32_t hp0 = (uint32_t)__bfloat16_as_ushort(h0) |
                           ((uint32_t)__bfloat16_as_ushort(h1) << 16);
            uint32_t hp1 = (uint32_t)__bfloat16_as_ushort(h2) |
                           ((uint32_t)__bfloat16_as_ushort(h3) << 16);
            uint32_t lp0 = (uint32_t)__bfloat16_as_ushort(l0) |
                           ((uint32_t)__bfloat16_as_ushort(l1) << 16);
            uint32_t lp1 = (uint32_t)__bfloat16_as_ushort(l2) |
                           ((uint32_t)__bfloat16_as_ushort(l3) << 16);
            uint32_t off = row * 64 + q4 * 8;
            *(uint32_t*)(st + A_HI + off)     = hp0;
            *(uint32_t*)(st + A_HI + off + 4) = hp1;
            *(uint32_t*)(st + A_LO + off)     = lp0;
            *(uint32_t*)(st + A_LO + off + 4) = lp1;
        }
#pragma unroll
        for (int it = 0; it < 6; it++) {
            int u = tid + it * 256;
            int v = (u < 768) ? u : (u - 768);
            int w = v >> 8, n = (v & 255) >> 2, q = v & 3;
            uint32_t off = (uint32_t)(w * 4096 + n * 64 + q * 16);
            *(uint4*)(st + ((u < 768) ? B_HI : B_LO) + off) = wr[it];
        }
        __syncthreads();

        // ---- prefetch next chunk while MMA runs ----
        if (c + 1 < NCHUNK) {
            const int k0 = (c + 1) * KC;
#pragma unroll
            for (int it = 0; it < 4; it++) {
                int f = tid + it * 256;
                int row = f >> 3, q4 = f & 7;
                xr[it] = *(const float4*)&x[(size_t)(m0 + row) * CC + k0 + q4 * 4];
            }
            const uint4* whi = (const uint4*)g_whi;
            const uint4* wlo = (const uint4*)g_wlo;
#pragma unroll
            for (int it = 0; it < 6; it++) {
                int u = tid + it * 256;
                int v = (u < 768) ? u : (u - 768);
                int w = v >> 8, n = (v & 255) >> 2, q = v & 3;
                uint32_t src = (uint32_t)(w * (HH * CC) + n * CC + k0) / 8 + q;
                wr[it] = (u < 768) ? whi[src] : wlo[src];
            }
        }

        // ---- MMA on current buffer ----
#pragma unroll
        for (int ks = 0; ks < 2; ks++) {
            uint32_t ah[4], al[4];
            ldsm4(ah, stb + A_HI + aoff + ks * 32);
            ldsm4(al, stb + A_LO + aoff + ks * 32);
#pragma unroll
            for (int w = 0; w < 3; w++) {
#pragma unroll
                for (int ng = 0; ng < 4; ng++) {
                    uint32_t bh[4], bl[4];
                    uint32_t bo = boff + (uint32_t)(ng * 16 * 64 + ks * 32 + w * 4096);
                    ldsm4(bh, stb + B_HI + bo);
                    ldsm4(bl, stb + B_LO + bo);
                    mma16816(acc[w][2 * ng],     ah, bh[0], bh[1]);
                    mma16816(acc[w][2 * ng],     ah, bl[0], bl[1]);
                    mma16816(acc[w][2 * ng],     al, bh[0], bh[1]);
                    mma16816(acc[w][2 * ng + 1], ah, bh[2], bh[3]);
                    mma16816(acc[w][2 * ng + 1], ah, bl[2], bl[3]);
                    mma16816(acc[w][2 * ng + 1], al, bh[2], bh[3]);
                }
            }
        }
        __syncthreads();
    }

    // ---- epilogue: write fp32 k/q/v ----
    float* outs[3] = {g_k, g_q, g_v};
    const int row_lo = m0 + wid * 16 + (lane >> 2);
#pragma unroll
    for (int w = 0; w < 3; w++) {
        float* op = outs[w];
#pragma unroll
        for (int nt = 0; nt < 8; nt++) {
            int col = nt * 8 + (lane & 3) * 2;
            *(float2*)&op[(size_t)row_lo * HH + col] =
                make_float2(acc[w][nt][0], acc[w][nt][1]);
            *(float2*)&op[(size_t)(row_lo + 8) * HH + col] =
                make_float2(acc[w][nt][2], acc[w][nt][3]);
        }
    }
}

// ---------------------------------------------------------------------------
// Kernel 2: flash attention (causal), split over key range into NSPLIT chunks.
// Grid (T/128, B, NSPLIT). 128 threads; thread = one query row. 2 CTAs/SM.
// ---------------------------------------------------------------------------
__global__ __launch_bounds__(128, 2) void attn_kernel()
{
    const int qtile = blockIdx.x;
    const int b = blockIdx.y;
    const int split = blockIdx.z;
    const int tid = threadIdx.x;

    const int t = qtile * 128 + tid;
    const int tmax = qtile * 128 + 127;
    const int ks0 = split * SPLIT_LEN;
    const int ks1 = min((split + 1) * SPLIT_LEN, tmax + 1);

    __shared__ float sk[64][64];
    __shared__ float sv[64][64];

    float q[HH];
    {
        const float* qr = g_q + (size_t)(b * TT + t) * HH;
#pragma unroll
        for (int h4 = 0; h4 < 16; h4++) {
            float4 v = *(const float4*)&qr[h4 * 4];
            q[h4 * 4 + 0] = v.x; q[h4 * 4 + 1] = v.y;
            q[h4 * 4 + 2] = v.z; q[h4 * 4 + 3] = v.w;
        }
    }

    float o[HH];
#pragma unroll
    for (int h = 0; h < HH; h++) o[h] = 0.f;
    float m = -1e30f;
    float l = 0.f;
    const float scale = 0.125f;

    for (int s0 = ks0; s0 < ks1; s0 += 64) {
        __syncthreads();
#pragma unroll
        for (int i = 0; i < 8; i++) {
            int f = tid + i * 128;
            int row = f >> 4;
            int c4 = (f & 15) * 4;
            *(float4*)&sk[row][c4] = *(const float4*)&g_k[(size_t)(b * TT + s0 + row) * HH + c4];
            *(float4*)&sv[row][c4] = *(const float4*)&g_v[(size_t)(b * TT + s0 + row) * HH + c4];
        }
        __syncthreads();

        const int send = min(ks1, t + 1) - s0;

        for (int s = 0; s < 64; s++) {
            if (s < send) {
                float4 accA = make_float4(0.f, 0.f, 0.f, 0.f);
                float4 accB = make_float4(0.f, 0.f, 0.f, 0.f);
#pragma unroll
                for (int h4 = 0; h4 < 16; h4 += 2) {
                    float4 k0v = *(const float4*)&sk[s][h4 * 4];
                    float4 k1v = *(const float4*)&sk[s][h4 * 4 + 4];
                    accA.x += q[h4 * 4 + 0] * k0v.x;
                    accA.y += q[h4 * 4 + 1] * k0v.y;
                    accA.z += q[h4 * 4 + 2] * k0v.z;
                    accA.w += q[h4 * 4 + 3] * k0v.w;
                    accB.x += q[h4 * 4 + 4] * k1v.x;
                    accB.y += q[h4 * 4 + 5] * k1v.y;
                    accB.z += q[h4 * 4 + 6] * k1v.z;
                    accB.w += q[h4 * 4 + 7] * k1v.w;
                }
                float sc = ((accA.x + accA.y) + (accA.z + accA.w)) +
                           ((accB.x + accB.y) + (accB.z + accB.w));
                sc *= scale;

                if (sc > m) {
                    float corr = __expf(m - sc);
                    m = sc;
                    l *= corr;
#pragma unroll
                    for (int h = 0; h < HH; h++) o[h] *= corr;
                }
                float p = __expf(sc - m);
                l += p;
#pragma unroll
                for (int h4 = 0; h4 < 16; h4++) {
                    float4 vv = *(const float4*)&sv[s][h4 * 4];
                    o[h4 * 4 + 0] += p * vv.x;
                    o[h4 * 4 + 1] += p * vv.y;
                    o[h4 * 4 + 2] += p * vv.z;
                    o[h4 * 4 + 3] += p * vv.w;
                }
            }
        }
    }

    const int row = b * TT + t;
    g_pm[split * BT + row] = m;
    g_pl[split * BT + row] = l;
    float* po = g_po + ((size_t)split * BT + row) * HH;
#pragma unroll
    for (int h4 = 0; h4 < 16; h4++) {
        float4 v = make_float4(o[h4 * 4 + 0], o[h4 * 4 + 1],
                               o[h4 * 4 + 2], o[h4 * 4 + 3]);
        *(float4*)&po[h4 * 4] = v;
    }
}

// ---------------------------------------------------------------------------
// Kernel 3: combine partials.
// ---------------------------------------------------------------------------
__global__ __launch_bounds__(64) void combine_kernel(float* __restrict__ out)
{
    const int row = blockIdx.x;
    const int h = threadIdx.x;

    float mv[NSPLIT], lv[NSPLIT];
#pragma unroll
    for (int i = 0; i < NSPLIT; i++) {
        mv[i] = g_pm[i * BT + row];
        lv[i] = g_pl[i * BT + row];
    }
    float M = mv[0];
#pragma unroll
    for (int i = 1; i < NSPLIT; i++) M = fmaxf(M, mv[i]);

    float L = 0.f, acc = 0.f;
#pragma unroll
    for (int i = 0; i < NSPLIT; i++) {
        float w = __expf(mv[i] - M);
        L += lv[i] * w;
        acc += g_po[((size_t)i * BT + row) * HH + h] * w;
    }
    out[(size_t)row * HH + h] = acc / L;
}

// ---------------------------------------------------------------------------
extern "C" void kernel_launch(void* const* d_in, const int* in_sizes, int n_in,
                              void* d_out, int out_size)
{
    const float* x  = (const float*)d_in[0];
    const float* Wk = (const float*)d_in[1];
    const float* Wq = (const float*)d_in[2];
    const float* Wv = (const float*)d_in[3];
    float* out = (float*)d_out;

    static bool attr_set = false;
    if (!attr_set) {
        cudaFuncSetAttribute(qkv_mma_kernel,
                             cudaFuncAttributeMaxDynamicSharedMemorySize, QKV_SMEM);
        attr_set = true;
    }

    prep_w_kernel<<<3 * HH * CC / 256, 256>>>(Wk, Wq, Wv);
    qkv_mma_kernel<<<BT / 128, 256, QKV_SMEM>>>(x);
    attn_kernel<<<dim3(TT / 128, BB, NSPLIT), 128>>>();
    combine_kernel<<<dim3(BT), 64>>>(out);
}

// round 7
// speedup vs baseline: 1.9850x; 1.8759x over previous
#include <cuda_runtime.h>
#include <cuda_bf16.h>
#include <cuda_fp16.h>
#include <cstdint>

// Problem constants
#define BB 8
#define TT 2048
#define CC 1024
#define HH 64
#define BT (BB * TT)             // 16384 rows
#define NSPLIT 4
#define SPLIT_LEN (TT / NSPLIT)  // 512

// Scratch (device globals: allocation-free rule)
__device__ float g_q[BT * HH];
__device__ float g_k[BT * HH];
__device__ float g_v[BT * HH];
__device__ float g_pm[NSPLIT * BT];
__device__ float g_pl[NSPLIT * BT];
__device__ float g_po[NSPLIT * BT * HH];
// W split into bf16 hi/lo, transposed to [w][n][k] (K-major rows of 1024)
__device__ __align__(16) __nv_bfloat16 g_whi[3 * HH * CC];
__device__ __align__(16) __nv_bfloat16 g_wlo[3 * HH * CC];

// ---------------------------------------------------------------------------
// mma.sync / ldmatrix helpers
// ---------------------------------------------------------------------------
__device__ __forceinline__ uint32_t smem_u32(const void* p) {
    uint32_t a;
    asm("{ .reg .u64 t; cvta.to.shared.u64 t, %1; cvt.u32.u64 %0, t; }"
        : "=r"(a) : "l"(p));
    return a;
}

__device__ __forceinline__ void ldsm4(uint32_t* r, uint32_t addr) {
    asm volatile("ldmatrix.sync.aligned.m8n8.x4.shared.b16 {%0,%1,%2,%3}, [%4];"
                 : "=r"(r[0]), "=r"(r[1]), "=r"(r[2]), "=r"(r[3]) : "r"(addr));
}

__device__ __forceinline__ void mma16816(float* c, const uint32_t* a,
                                         uint32_t b0, uint32_t b1) {
    asm volatile(
        "mma.sync.aligned.m16n8k16.row.col.f32.bf16.bf16.f32 "
        "{%0,%1,%2,%3}, {%4,%5,%6,%7}, {%8,%9}, {%0,%1,%2,%3};"
        : "+f"(c[0]), "+f"(c[1]), "+f"(c[2]), "+f"(c[3])
        : "r"(a[0]), "r"(a[1]), "r"(a[2]), "r"(a[3]), "r"(b0), "r"(b1));
}

__device__ __forceinline__ void mma16816h(float* c, const uint32_t* a,
                                          uint32_t b0, uint32_t b1) {
    asm volatile(
        "mma.sync.aligned.m16n8k16.row.col.f32.f16.f16.f32 "
        "{%0,%1,%2,%3}, {%4,%5,%6,%7}, {%8,%9}, {%0,%1,%2,%3};"
        : "+f"(c[0]), "+f"(c[1]), "+f"(c[2]), "+f"(c[3])
        : "r"(a[0]), "r"(a[1]), "r"(a[2]), "r"(a[3]), "r"(b0), "r"(b1));
}

__device__ __forceinline__ uint32_t f2h2(float a, float b) {
    __half2 h = __floats2half2_rn(a, b);
    return *(uint32_t*)&h;
}

// ---------------------------------------------------------------------------
// Kernel 0: split W into bf16 hi/lo, transposed to [w][n][k]
// ---------------------------------------------------------------------------
__global__ __launch_bounds__(256) void prep_w_kernel(
    const float* __restrict__ Wk, const float* __restrict__ Wq,
    const float* __restrict__ Wv)
{
    int i = blockIdx.x * 256 + threadIdx.x;   // over 3*64*1024
    int w = i >> 16;
    int rem = i & 65535;
    int n = rem >> 10;
    int k = rem & 1023;
    const float* W = (w == 0) ? Wk : (w == 1) ? Wq : Wv;
    float v = W[k * HH + n];
    __nv_bfloat16 h = __float2bfloat16(v);
    float r = v - __bfloat162float(h);
    g_whi[i] = h;
    g_wlo[i] = __float2bfloat16(r);
}

// ---------------------------------------------------------------------------
// Kernel 1: QKV projection via mma.sync (bf16 split precision, fp32 accum).
// (unchanged from passing R4 kernel)
// ---------------------------------------------------------------------------
#define KC 32
#define NCHUNK (CC / KC)        // 32
#define A_HI 0
#define A_LO 8192
#define B_HI 16384              // + w*4096
#define B_LO 28672              // + w*4096
#define STAGE 40960
#define QKV_SMEM (2 * STAGE)

__global__ __launch_bounds__(256, 1) void qkv_mma_kernel(const float* __restrict__ x)
{
    extern __shared__ __align__(16) char sm[];
    const uint32_t sbase = smem_u32(sm);

    const int tid = threadIdx.x;
    const int wid = tid >> 5;
    const int lane = tid & 31;
    const int m0 = blockIdx.x * 128;

    const uint32_t aoff = (uint32_t)((wid * 16 + (lane & 15)) * 64 + ((lane >> 4) * 16));
    const uint32_t boff = (uint32_t)(((lane & 7) + ((lane >> 4) << 3)) * 64 +
                                     (((lane >> 3) & 1) * 16));

    float acc[3][8][4];
#pragma unroll
    for (int w = 0; w < 3; w++)
#pragma unroll
        for (int nt = 0; nt < 8; nt++)
#pragma unroll
            for (int j = 0; j < 4; j++) acc[w][nt][j] = 0.f;

    float4 xr[4];
    uint4 wr[6];

    {
        const int k0 = 0;
#pragma unroll
        for (int it = 0; it < 4; it++) {
            int f = tid + it * 256;
            int row = f >> 3, q4 = f & 7;
            xr[it] = *(const float4*)&x[(size_t)(m0 + row) * CC + k0 + q4 * 4];
        }
        const uint4* whi = (const uint4*)g_whi;
        const uint4* wlo = (const uint4*)g_wlo;
#pragma unroll
        for (int it = 0; it < 6; it++) {
            int u = tid + it * 256;
            int v = (u < 768) ? u : (u - 768);
            int w = v >> 8, n = (v & 255) >> 2, q = v & 3;
            uint32_t src = (uint32_t)(w * (HH * CC) + n * CC + k0) / 8 + q;
            wr[it] = (u < 768) ? whi[src] : wlo[src];
        }
    }

    for (int c = 0; c < NCHUNK; c++) {
        const int buf = c & 1;
        char* st = sm + buf * STAGE;
        const uint32_t stb = sbase + buf * STAGE;

#pragma unroll
        for (int it = 0; it < 4; it++) {
            int f = tid + it * 256;
            int row = f >> 3, q4 = f & 7;
            float4 v = xr[it];
            __nv_bfloat16 h0 = __float2bfloat16(v.x);
            __nv_bfloat16 h1 = __float2bfloat16(v.y);
            __nv_bfloat16 h2 = __float2bfloat16(v.z);
            __nv_bfloat16 h3 = __float2bfloat16(v.w);
            __nv_bfloat16 l0 = __float2bfloat16(v.x - __bfloat162float(h0));
            __nv_bfloat16 l1 = __float2bfloat16(v.y - __bfloat162float(h1));
            __nv_bfloat16 l2 = __float2bfloat16(v.z - __bfloat162float(h2));
            __nv_bfloat16 l3 = __float2bfloat16(v.w - __bfloat162float(h3));
            uint32_t hp0 = (uint32_t)__bfloat16_as_ushort(h0) |
                           ((uint32_t)__bfloat16_as_ushort(h1) << 16);
            uint32_t hp1 = (uint32_t)__bfloat16_as_ushort(h2) |
                           ((uint32_t)__bfloat16_as_ushort(h3) << 16);
            uint32_t lp0 = (uint32_t)__bfloat16_as_ushort(l0) |
                           ((uint32_t)__bfloat16_as_ushort(l1) << 16);
            uint32_t lp1 = (uint32_t)__bfloat16_as_ushort(l2) |
                           ((uint32_t)__bfloat16_as_ushort(l3) << 16);
            uint32_t off = row * 64 + q4 * 8;
            *(uint32_t*)(st + A_HI + off)     = hp0;
            *(uint32_t*)(st + A_HI + off + 4) = hp1;
            *(uint32_t*)(st + A_LO + off)     = lp0;
            *(uint32_t*)(st + A_LO + off + 4) = lp1;
        }
#pragma unroll
        for (int it = 0; it < 6; it++) {
            int u = tid + it * 256;
            int v = (u < 768) ? u : (u - 768);
            int w = v >> 8, n = (v & 255) >> 2, q = v & 3;
            uint32_t off = (uint32_t)(w * 4096 + n * 64 + q * 16);
            *(uint4*)(st + ((u < 768) ? B_HI : B_LO) + off) = wr[it];
        }
        __syncthreads();

        if (c + 1 < NCHUNK) {
            const int k0 = (c + 1) * KC;
#pragma unroll
            for (int it = 0; it < 4; it++) {
                int f = tid + it * 256;
                int row = f >> 3, q4 = f & 7;
                xr[it] = *(const float4*)&x[(size_t)(m0 + row) * CC + k0 + q4 * 4];
            }
            const uint4* whi = (const uint4*)g_whi;
            const uint4* wlo = (const uint4*)g_wlo;
#pragma unroll
            for (int it = 0; it < 6; it++) {
                int u = tid + it * 256;
                int v = (u < 768) ? u : (u - 768);
                int w = v >> 8, n = (v & 255) >> 2, q = v & 3;
                uint32_t src = (uint32_t)(w * (HH * CC) + n * CC + k0) / 8 + q;
                wr[it] = (u < 768) ? whi[src] : wlo[src];
            }
        }

#pragma unroll
        for (int ks = 0; ks < 2; ks++) {
            uint32_t ah[4], al[4];
            ldsm4(ah, stb + A_HI + aoff + ks * 32);
            ldsm4(al, stb + A_LO + aoff + ks * 32);
#pragma unroll
            for (int w = 0; w < 3; w++) {
#pragma unroll
                for (int ng = 0; ng < 4; ng++) {
                    uint32_t bh[4], bl[4];
                    uint32_t bo = boff + (uint32_t)(ng * 16 * 64 + ks * 32 + w * 4096);
                    ldsm4(bh, stb + B_HI + bo);
                    ldsm4(bl, stb + B_LO + bo);
                    mma16816(acc[w][2 * ng],     ah, bh[0], bh[1]);
                    mma16816(acc[w][2 * ng],     ah, bl[0], bl[1]);
                    mma16816(acc[w][2 * ng],     al, bh[0], bh[1]);
                    mma16816(acc[w][2 * ng + 1], ah, bh[2], bh[3]);
                    mma16816(acc[w][2 * ng + 1], ah, bl[2], bl[3]);
                    mma16816(acc[w][2 * ng + 1], al, bh[2], bh[3]);
                }
            }
        }
        __syncthreads();
    }

    float* outs[3] = {g_k, g_q, g_v};
    const int row_lo = m0 + wid * 16 + (lane >> 2);
#pragma unroll
    for (int w = 0; w < 3; w++) {
        float* op = outs[w];
#pragma unroll
        for (int nt = 0; nt < 8; nt++) {
            int col = nt * 8 + (lane & 3) * 2;
            *(float2*)&op[(size_t)row_lo * HH + col] =
                make_float2(acc[w][nt][0], acc[w][nt][1]);
            *(float2*)&op[(size_t)(row_lo + 8) * HH + col] =
                make_float2(acc[w][nt][2], acc[w][nt][3]);
        }
    }
}

// ---------------------------------------------------------------------------
// Kernel 2: FA-2 style flash attention with mma.sync (fp16), causal, split-K.
// Grid (TT/128, BB, NSPLIT), 256 threads. Warp w owns q rows [w*16, w*16+16).
// ---------------------------------------------------------------------------
__global__ __launch_bounds__(256, 2) void attn_mma_kernel()
{
    __shared__ __align__(128) char sQ[128 * 128];   // 16KB
    __shared__ __align__(128) char sK[64 * 128];    // 8KB
    __shared__ __align__(128) char sV[64 * 128];    // 8KB (V^T: [h][key])

    const int qtile = blockIdx.x;
    const int b = blockIdx.y;
    const int split = blockIdx.z;
    const int tid = threadIdx.x;
    const int wid = tid >> 5;
    const int lane = tid & 31;

    const int qrow0 = qtile * 128;
    const int ks0 = split * SPLIT_LEN;
    const int ks1 = min((split + 1) * SPLIT_LEN, qrow0 + 128);

    const uint32_t sQb = smem_u32(sQ);
    const uint32_t sKb = smem_u32(sK);
    const uint32_t sVb = smem_u32(sV);

    // ---- stage Q (fp16, swizzled) ----
#pragma unroll
    for (int i = 0; i < 8; i++) {
        int f = tid + i * 256;              // 2048 float4: 128 rows x 16
        int row = f >> 4, h4 = f & 15;
        float4 v = *(const float4*)&g_q[(size_t)(b * TT + qrow0 + row) * HH + h4 * 4];
        int chunk = h4 >> 1;
        uint32_t addr = (uint32_t)(row * 128 + ((chunk ^ (row & 7)) * 16) + (h4 & 1) * 8);
        *(uint32_t*)(sQ + addr)     = f2h2(v.x, v.y);
        *(uint32_t*)(sQ + addr + 4) = f2h2(v.z, v.w);
    }
    __syncthreads();

    // ---- load Q fragments (held for whole kernel) ----
    uint32_t aq[4][4];
    {
        int row = wid * 16 + (lane & 15);
#pragma unroll
        for (int ks = 0; ks < 4; ks++) {
            int chunk = 2 * ks + (lane >> 4);
            uint32_t addr = sQb + (uint32_t)(row * 128 + ((chunk ^ (row & 7)) * 16));
            ldsm4(aq[ks], addr);
        }
    }

    // ---- accumulators ----
    float o[8][4];
#pragma unroll
    for (int ng = 0; ng < 8; ng++)
#pragma unroll
        for (int j = 0; j < 4; j++) o[ng][j] = 0.f;
    float m0 = -1e30f, m1 = -1e30f, l0 = 0.f, l1 = 0.f;

    const int t0 = qrow0 + wid * 16 + (lane >> 2);  // my fragment rows
    const int t1 = t0 + 8;
    const int wmin = qrow0 + wid * 16;              // warp's first row
    const int wmax = wmin + 15;                     // warp's last row
    const float scale = 0.125f;

    for (int s0 = ks0; s0 < ks1; s0 += 64) {
        __syncthreads();
        // ---- stage K [key][h] and V^T [h][key] ----
#pragma unroll
        for (int i = 0; i < 4; i++) {
            int f = tid + i * 256;          // 1024 float4: 64 keys x 16
            int key = f >> 4, h4 = f & 15;
            float4 kv = *(const float4*)&g_k[(size_t)(b * TT + s0 + key) * HH + h4 * 4];
            int chunk = h4 >> 1;
            uint32_t addr = (uint32_t)(key * 128 + ((chunk ^ (key & 7)) * 16) + (h4 & 1) * 8);
            *(uint32_t*)(sK + addr)     = f2h2(kv.x, kv.y);
            *(uint32_t*)(sK + addr + 4) = f2h2(kv.z, kv.w);

            float4 vv = *(const float4*)&g_v[(size_t)(b * TT + s0 + key) * HH + h4 * 4];
            int h0 = h4 * 4;
            __half hv[4] = {__float2half_rn(vv.x), __float2half_rn(vv.y),
                            __float2half_rn(vv.z), __float2half_rn(vv.w)};
#pragma unroll
            for (int j = 0; j < 4; j++) {
                int h = h0 + j;
                uint32_t vaddr = (uint32_t)(h * 128 + (((key >> 3) ^ (h & 7)) * 16) +
                                            (key & 7) * 2);
                *(__half*)(sV + vaddr) = hv[j];
            }
        }
        __syncthreads();

        if (s0 > wmax) continue;   // tile fully above this warp's rows

        // ---- S = Q K^T ----
        float s[8][4];
#pragma unroll
        for (int ng = 0; ng < 8; ng++)
#pragma unroll
            for (int j = 0; j < 4; j++) s[ng][j] = 0.f;

#pragma unroll
        for (int kg = 0; kg < 4; kg++) {
            int rowB = kg * 16 + (lane & 7) + ((lane >> 4) << 3);
#pragma unroll
            for (int ks = 0; ks < 4; ks++) {
                int chunk = ((lane >> 3) & 1) + 2 * ks;
                uint32_t addr = sKb + (uint32_t)(rowB * 128 + ((chunk ^ (rowB & 7)) * 16));
                uint32_t bk[4];
                ldsm4(bk, addr);
                mma16816h(s[2 * kg],     aq[ks], bk[0], bk[1]);
                mma16816h(s[2 * kg + 1], aq[ks], bk[2], bk[3]);
            }
        }

        // ---- scale + causal mask ----
        // Masking needed whenever the tile's max key can exceed the warp's
        // FIRST row (fixed from R6: was wmax, which skipped masking for
        // 3/4 of warps' diagonal tiles).
        const bool diag = (s0 + 63 >= wmin);
#pragma unroll
        for (int ng = 0; ng < 8; ng++) {
            int scol = s0 + ng * 8 + (lane & 3) * 2;
            if (diag) {
                s[ng][0] = (scol     > t0) ? -1e30f : s[ng][0] * scale;
                s[ng][1] = (scol + 1 > t0) ? -1e30f : s[ng][1] * scale;
                s[ng][2] = (scol     > t1) ? -1e30f : s[ng][2] * scale;
                s[ng][3] = (scol + 1 > t1) ? -1e30f : s[ng][3] * scale;
            } else {
                s[ng][0] *= scale; s[ng][1] *= scale;
                s[ng][2] *= scale; s[ng][3] *= scale;
            }
        }

        // ---- online softmax ----
        float mx0 = -1e30f, mx1 = -1e30f;
#pragma unroll
        for (int ng = 0; ng < 8; ng++) {
            mx0 = fmaxf(mx0, fmaxf(s[ng][0], s[ng][1]));
            mx1 = fmaxf(mx1, fmaxf(s[ng][2], s[ng][3]));
        }
        mx0 = fmaxf(mx0, __shfl_xor_sync(0xffffffffu, mx0, 1));
        mx0 = fmaxf(mx0, __shfl_xor_sync(0xffffffffu, mx0, 2));
        mx1 = fmaxf(mx1, __shfl_xor_sync(0xffffffffu, mx1, 1));
        mx1 = fmaxf(mx1, __shfl_xor_sync(0xffffffffu, mx1, 2));

        float mn0 = fmaxf(m0, mx0);
        float mn1 = fmaxf(m1, mx1);
        float c0 = __expf(m0 - mn0);
        float c1 = __expf(m1 - mn1);

        float sum0 = 0.f, sum1 = 0.f;
#pragma unroll
        for (int ng = 0; ng < 8; ng++) {
            s[ng][0] = __expf(s[ng][0] - mn0);
            s[ng][1] = __expf(s[ng][1] - mn0);
            s[ng][2] = __expf(s[ng][2] - mn1);
            s[ng][3] = __expf(s[ng][3] - mn1);
            sum0 += s[ng][0] + s[ng][1];
            sum1 += s[ng][2] + s[ng][3];
        }
        sum0 += __shfl_xor_sync(0xffffffffu, sum0, 1);
        sum0 += __shfl_xor_sync(0xffffffffu, sum0, 2);
        sum1 += __shfl_xor_sync(0xffffffffu, sum1, 1);
        sum1 += __shfl_xor_sync(0xffffffffu, sum1, 2);

        l0 = l0 * c0 + sum0;
        l1 = l1 * c1 + sum1;
        m0 = mn0; m1 = mn1;

#pragma unroll
        for (int ng = 0; ng < 8; ng++) {
            o[ng][0] *= c0; o[ng][1] *= c0;
            o[ng][2] *= c1; o[ng][3] *= c1;
        }

        // ---- O += P V ----
#pragma unroll
        for (int ks = 0; ks < 4; ks++) {
            uint32_t ap[4];
            ap[0] = f2h2(s[2 * ks][0],     s[2 * ks][1]);
            ap[1] = f2h2(s[2 * ks][2],     s[2 * ks][3]);
            ap[2] = f2h2(s[2 * ks + 1][0], s[2 * ks + 1][1]);
            ap[3] = f2h2(s[2 * ks + 1][2], s[2 * ks + 1][3]);
#pragma unroll
            for (int hg = 0; hg < 4; hg++) {
                int rowV = hg * 16 + (lane & 7) + ((lane >> 4) << 3);
                int chunk = ((lane >> 3) & 1) + 2 * ks;
                uint32_t addr = sVb + (uint32_t)(rowV * 128 + ((chunk ^ (rowV & 7)) * 16));
                uint32_t bv[4];
                ldsm4(bv, addr);
                mma16816h(o[2 * hg],     ap, bv[0], bv[1]);
                mma16816h(o[2 * hg + 1], ap, bv[2], bv[3]);
            }
        }
    }

    // ---- write partials ----
    const int grow0 = b * TT + t0;
    const int grow1 = b * TT + t1;
    if ((lane & 3) == 0) {
        g_pm[split * BT + grow0] = m0;
        g_pl[split * BT + grow0] = l0;
        g_pm[split * BT + grow1] = m1;
        g_pl[split * BT + grow1] = l1;
    }
    float* po0 = g_po + ((size_t)split * BT + grow0) * HH;
    float* po1 = g_po + ((size_t)split * BT + grow1) * HH;
#pragma unroll
    for (int ng = 0; ng < 8; ng++) {
        int col = ng * 8 + (lane & 3) * 2;
        *(float2*)&po0[col] = make_float2(o[ng][0], o[ng][1]);
        *(float2*)&po1[col] = make_float2(o[ng][2], o[ng][3]);
    }
}

// ---------------------------------------------------------------------------
// Kernel 3: combine partials.
// ---------------------------------------------------------------------------
__global__ __launch_bounds__(64) void combine_kernel(float* __restrict__ out)
{
    const int row = blockIdx.x;
    const int h = threadIdx.x;

    float mv[NSPLIT], lv[NSPLIT];
#pragma unroll
    for (int i = 0; i < NSPLIT; i++) {
        mv[i] = g_pm[i * BT + row];
        lv[i] = g_pl[i * BT + row];
    }
    float M = mv[0];
#pragma unroll
    for (int i = 1; i < NSPLIT; i++) M = fmaxf(M, mv[i]);

    float L = 0.f, acc = 0.f;
#pragma unroll
    for (int i = 0; i < NSPLIT; i++) {
        float w = __expf(mv[i] - M);
        L += lv[i] * w;
        acc += g_po[((size_t)i * BT + row) * HH + h] * w;
    }
    out[(size_t)row * HH + h] = acc / L;
}

// ---------------------------------------------------------------------------
extern "C" void kernel_launch(void* const* d_in, const int* in_sizes, int n_in,
                              void* d_out, int out_size)
{
    const float* x  = (const float*)d_in[0];
    const float* Wk = (const float*)d_in[1];
    const float* Wq = (const float*)d_in[2];
    const float* Wv = (const float*)d_in[3];
    float* out = (float*)d_out;

    static bool attr_set = false;
    if (!attr_set) {
        cudaFuncSetAttribute(qkv_mma_kernel,
                             cudaFuncAttributeMaxDynamicSharedMemorySize, QKV_SMEM);
        attr_set = true;
    }

    prep_w_kernel<<<3 * HH * CC / 256, 256>>>(Wk, Wq, Wv);
    qkv_mma_kernel<<<BT / 128, 256, QKV_SMEM>>>(x);
    attn_mma_kernel<<<dim3(TT / 128, BB, NSPLIT), 256>>>();
    combine_kernel<<<dim3(BT), 64>>>(out);
}

// round 8
// speedup vs baseline: 3.3952x; 1.7104x over previous
#include <cuda_runtime.h>
#include <cuda_bf16.h>
#include <cuda_fp16.h>
#include <cstdint>

// Problem constants
#define BB 8
#define TT 2048
#define CC 1024
#define HH 64
#define BT (BB * TT)             // 16384 rows
#define NSPLIT 4
#define SPLIT_LEN (TT / NSPLIT)  // 512

// Scratch (device globals: allocation-free rule)
__device__ float g_q[BT * HH];
__device__ float g_k[BT * HH];
__device__ float g_v[BT * HH];
__device__ float g_pm[NSPLIT * BT];
__device__ float g_pl[NSPLIT * BT];
__device__ float g_po[NSPLIT * BT * HH];
// W split into bf16 hi/lo, transposed to [w][n][k] (K-major rows of 1024)
__device__ __align__(16) __nv_bfloat16 g_whi[3 * HH * CC];
__device__ __align__(16) __nv_bfloat16 g_wlo[3 * HH * CC];

// ---------------------------------------------------------------------------
// mma.sync / ldmatrix / cp.async helpers
// ---------------------------------------------------------------------------
__device__ __forceinline__ uint32_t smem_u32(const void* p) {
    uint32_t a;
    asm("{ .reg .u64 t; cvta.to.shared.u64 t, %1; cvt.u32.u64 %0, t; }"
        : "=r"(a) : "l"(p));
    return a;
}

__device__ __forceinline__ void ldsm4(uint32_t* r, uint32_t addr) {
    asm volatile("ldmatrix.sync.aligned.m8n8.x4.shared.b16 {%0,%1,%2,%3}, [%4];"
                 : "=r"(r[0]), "=r"(r[1]), "=r"(r[2]), "=r"(r[3]) : "r"(addr));
}

__device__ __forceinline__ void mma16816(float* c, const uint32_t* a,
                                         uint32_t b0, uint32_t b1) {
    asm volatile(
        "mma.sync.aligned.m16n8k16.row.col.f32.bf16.bf16.f32 "
        "{%0,%1,%2,%3}, {%4,%5,%6,%7}, {%8,%9}, {%0,%1,%2,%3};"
        : "+f"(c[0]), "+f"(c[1]), "+f"(c[2]), "+f"(c[3])
        : "r"(a[0]), "r"(a[1]), "r"(a[2]), "r"(a[3]), "r"(b0), "r"(b1));
}

__device__ __forceinline__ void mma16816h(float* c, const uint32_t* a,
                                          uint32_t b0, uint32_t b1) {
    asm volatile(
        "mma.sync.aligned.m16n8k16.row.col.f32.f16.f16.f32 "
        "{%0,%1,%2,%3}, {%4,%5,%6,%7}, {%8,%9}, {%0,%1,%2,%3};"
        : "+f"(c[0]), "+f"(c[1]), "+f"(c[2]), "+f"(c[3])
        : "r"(a[0]), "r"(a[1]), "r"(a[2]), "r"(a[3]), "r"(b0), "r"(b1));
}

__device__ __forceinline__ uint32_t f2h2(float a, float b) {
    __half2 h = __floats2half2_rn(a, b);
    return *(uint32_t*)&h;
}

__device__ __forceinline__ void cp16(uint32_t dst, const void* src) {
    asm volatile("cp.async.ca.shared.global [%0], [%1], 16;"
                 :: "r"(dst), "l"(src) : "memory");
}
#define CP_COMMIT() asm volatile("cp.async.commit_group;" ::: "memory")
#define CP_WAIT(n)  asm volatile("cp.async.wait_group %0;" :: "n"(n) : "memory")

// ---------------------------------------------------------------------------
// Kernel 0: split W into bf16 hi/lo, transposed to [w][n][k]
// ---------------------------------------------------------------------------
__global__ __launch_bounds__(256) void prep_w_kernel(
    const float* __restrict__ Wk, const float* __restrict__ Wq,
    const float* __restrict__ Wv)
{
    int i = blockIdx.x * 256 + threadIdx.x;   // over 3*64*1024
    int w = i >> 16;
    int rem = i & 65535;
    int n = rem >> 10;
    int k = rem & 1023;
    const float* W = (w == 0) ? Wk : (w == 1) ? Wq : Wv;
    float v = W[k * HH + n];
    __nv_bfloat16 h = __float2bfloat16(v);
    float r = v - __bfloat162float(h);
    g_whi[i] = h;
    g_wlo[i] = __float2bfloat16(r);
}

// ---------------------------------------------------------------------------
// Kernel 1: QKV projection via mma.sync (bf16 split precision, fp32 accum).
// KC=64, 128-byte swizzled smem rows (conflict-free ldmatrix), B via cp.async.
// CTA: 128 rows x (3 outputs x 64 cols); 8 warps; warp owns 16 rows.
// ---------------------------------------------------------------------------
#define KC2 64
#define NCHUNK2 (CC / KC2)      // 16
#define QA_HI 0
#define QA_LO 16384
#define QB_HI 32768             // + w*8192
#define QB_LO 57344             // + w*8192
#define QSTAGE 81920
#define QKV_SMEM (2 * QSTAGE)   // 160 KB

__global__ __launch_bounds__(256, 1) void qkv_mma_kernel(const float* __restrict__ x)
{
    extern __shared__ __align__(128) char sm[];
    const uint32_t sbase = smem_u32(sm);

    const int tid = threadIdx.x;
    const int wid = tid >> 5;
    const int lane = tid & 31;
    const int m0 = blockIdx.x * 128;

    float acc[3][8][4];
#pragma unroll
    for (int w = 0; w < 3; w++)
#pragma unroll
        for (int nt = 0; nt < 8; nt++)
#pragma unroll
            for (int j = 0; j < 4; j++) acc[w][nt][j] = 0.f;

    // A-prefetch register file: 128 rows x 64 k fp32 = 2048 float4 / 256 thr
    float4 xr[8];

    // B cp.async issue for one chunk into stage `st` (hi + lo, 12 x 16B/thread)
    auto issue_b = [&](int k0, uint32_t stb) {
#pragma unroll
        for (int it = 0; it < 6; it++) {
            int g = tid + it * 256;            // 0..1535
            int w = g >> 9;                    // 0..2 (512 = 64n * 8 chunks)
            int n = (g >> 3) & 63;
            int ch = g & 7;
            uint32_t dst = stb + (uint32_t)(w * 8192 + n * 128 + ((ch ^ (n & 7)) * 16));
            const __nv_bfloat16* srch = g_whi + (size_t)w * (HH * CC) + n * CC + k0 + ch * 8;
            const __nv_bfloat16* srcl = g_wlo + (size_t)w * (HH * CC) + n * CC + k0 + ch * 8;
            cp16(QB_HI + dst, srch);
            cp16(QB_LO + dst, srcl);
        }
        CP_COMMIT();
    };

    auto load_a = [&](int k0) {
#pragma unroll
        for (int it = 0; it < 8; it++) {
            int f = tid + it * 256;            // row*16 + q4
            int row = f >> 4, q4 = f & 15;
            xr[it] = *(const float4*)&x[(size_t)(m0 + row) * CC + k0 + q4 * 4];
        }
    };

    // ---- prologue: chunk 0 ----
    load_a(0);
    issue_b(0, sbase);

    for (int c = 0; c < NCHUNK2; c++) {
        const int buf = c & 1;
        char* st = sm + buf * QSTAGE;
        const uint32_t stb = sbase + buf * QSTAGE;

        // ---- store A regs -> smem (convert fp32 -> bf16 hi/lo, swizzled) ----
#pragma unroll
        for (int it = 0; it < 8; it++) {
            int f = tid + it * 256;
            int row = f >> 4, q4 = f & 15;
            float4 v = xr[it];
            __nv_bfloat16 h0 = __float2bfloat16(v.x);
            __nv_bfloat16 h1 = __float2bfloat16(v.y);
            __nv_bfloat16 h2 = __float2bfloat16(v.z);
            __nv_bfloat16 h3 = __float2bfloat16(v.w);
            __nv_bfloat16 l0 = __float2bfloat16(v.x - __bfloat162float(h0));
            __nv_bfloat16 l1 = __float2bfloat16(v.y - __bfloat162float(h1));
            __nv_bfloat16 l2 = __float2bfloat16(v.z - __bfloat162float(h2));
            __nv_bfloat16 l3 = __float2bfloat16(v.w - __bfloat162float(h3));
            uint2 hp = make_uint2(
                (uint32_t)__bfloat16_as_ushort(h0) | ((uint32_t)__bfloat16_as_ushort(h1) << 16),
                (uint32_t)__bfloat16_as_ushort(h2) | ((uint32_t)__bfloat16_as_ushort(h3) << 16));
            uint2 lp = make_uint2(
                (uint32_t)__bfloat16_as_ushort(l0) | ((uint32_t)__bfloat16_as_ushort(l1) << 16),
                (uint32_t)__bfloat16_as_ushort(l2) | ((uint32_t)__bfloat16_as_ushort(l3) << 16));
            int ch = q4 >> 1;
            uint32_t off = (uint32_t)(row * 128 + ((ch ^ (row & 7)) * 16) + (q4 & 1) * 8);
            *(uint2*)(st + QA_HI + off) = hp;
            *(uint2*)(st + QA_LO + off) = lp;
        }

        // ---- prefetch next chunk (A regs + B cp.async into other buffer) ----
        if (c + 1 < NCHUNK2) {
            load_a((c + 1) * KC2);
            issue_b((c + 1) * KC2, sbase + (buf ^ 1) * QSTAGE);
            CP_WAIT(1);            // chunk c's B group done; c+1's may be pending
        } else {
            CP_WAIT(0);
        }
        __syncthreads();

        // ---- MMA on current buffer ----
        const int arow = wid * 16 + (lane & 15);
        const int browbase = (lane & 7) + ((lane >> 4) << 3);
        const int bchlo = (lane >> 3) & 1;
#pragma unroll
        for (int ks = 0; ks < 4; ks++) {
            uint32_t ah[4], al[4];
            {
                int ch = 2 * ks + (lane >> 4);
                uint32_t addr = stb + (uint32_t)(arow * 128 + ((ch ^ (arow & 7)) * 16));
                ldsm4(ah, QA_HI + addr);
                ldsm4(al, QA_LO + addr);
            }
#pragma unroll
            for (int w = 0; w < 3; w++) {
#pragma unroll
                for (int ng = 0; ng < 4; ng++) {
                    int rowB = ng * 16 + browbase;
                    int ch = bchlo + 2 * ks;
                    uint32_t addr = stb + (uint32_t)(w * 8192 + rowB * 128 +
                                                     ((ch ^ (rowB & 7)) * 16));
                    uint32_t bh[4], bl[4];
                    ldsm4(bh, QB_HI + addr);
                    ldsm4(bl, QB_LO + addr);
                    mma16816(acc[w][2 * ng],     ah, bh[0], bh[1]);
                    mma16816(acc[w][2 * ng],     ah, bl[0], bl[1]);
                    mma16816(acc[w][2 * ng],     al, bh[0], bh[1]);
                    mma16816(acc[w][2 * ng + 1], ah, bh[2], bh[3]);
                    mma16816(acc[w][2 * ng + 1], ah, bl[2], bl[3]);
                    mma16816(acc[w][2 * ng + 1], al, bh[2], bh[3]);
                }
            }
        }
        __syncthreads();
    }

    // ---- epilogue: write fp32 k/q/v ----
    float* outs[3] = {g_k, g_q, g_v};
    const int row_lo = m0 + wid * 16 + (lane >> 2);
#pragma unroll
    for (int w = 0; w < 3; w++) {
        float* op = outs[w];
#pragma unroll
        for (int nt = 0; nt < 8; nt++) {
            int col = nt * 8 + (lane & 3) * 2;
            *(float2*)&op[(size_t)row_lo * HH + col] =
                make_float2(acc[w][nt][0], acc[w][nt][1]);
            *(float2*)&op[(size_t)(row_lo + 8) * HH + col] =
                make_float2(acc[w][nt][2], acc[w][nt][3]);
        }
    }
}

// ---------------------------------------------------------------------------
// Kernel 2: FA-2 style flash attention with mma.sync (fp16), causal, split-K.
// (unchanged from passing R7 kernel)
// ---------------------------------------------------------------------------
__global__ __launch_bounds__(256, 2) void attn_mma_kernel()
{
    __shared__ __align__(128) char sQ[128 * 128];
    __shared__ __align__(128) char sK[64 * 128];
    __shared__ __align__(128) char sV[64 * 128];

    const int qtile = blockIdx.x;
    const int b = blockIdx.y;
    const int split = blockIdx.z;
    const int tid = threadIdx.x;
    const int wid = tid >> 5;
    const int lane = tid & 31;

    const int qrow0 = qtile * 128;
    const int ks0 = split * SPLIT_LEN;
    const int ks1 = min((split + 1) * SPLIT_LEN, qrow0 + 128);

    const uint32_t sQb = smem_u32(sQ);
    const uint32_t sKb = smem_u32(sK);
    const uint32_t sVb = smem_u32(sV);

#pragma unroll
    for (int i = 0; i < 8; i++) {
        int f = tid + i * 256;
        int row = f >> 4, h4 = f & 15;
        float4 v = *(const float4*)&g_q[(size_t)(b * TT + qrow0 + row) * HH + h4 * 4];
        int chunk = h4 >> 1;
        uint32_t addr = (uint32_t)(row * 128 + ((chunk ^ (row & 7)) * 16) + (h4 & 1) * 8);
        *(uint32_t*)(sQ + addr)     = f2h2(v.x, v.y);
        *(uint32_t*)(sQ + addr + 4) = f2h2(v.z, v.w);
    }
    __syncthreads();

    uint32_t aq[4][4];
    {
        int row = wid * 16 + (lane & 15);
#pragma unroll
        for (int ks = 0; ks < 4; ks++) {
            int chunk = 2 * ks + (lane >> 4);
            uint32_t addr = sQb + (uint32_t)(row * 128 + ((chunk ^ (row & 7)) * 16));
            ldsm4(aq[ks], addr);
        }
    }

    float o[8][4];
#pragma unroll
    for (int ng = 0; ng < 8; ng++)
#pragma unroll
        for (int j = 0; j < 4; j++) o[ng][j] = 0.f;
    float m0 = -1e30f, m1 = -1e30f, l0 = 0.f, l1 = 0.f;

    const int t0 = qrow0 + wid * 16 + (lane >> 2);
    const int t1 = t0 + 8;
    const int wmin = qrow0 + wid * 16;
    const int wmax = wmin + 15;
    const float scale = 0.125f;

    for (int s0 = ks0; s0 < ks1; s0 += 64) {
        __syncthreads();
#pragma unroll
        for (int i = 0; i < 4; i++) {
            int f = tid + i * 256;
            int key = f >> 4, h4 = f & 15;
            float4 kv = *(const float4*)&g_k[(size_t)(b * TT + s0 + key) * HH + h4 * 4];
            int chunk = h4 >> 1;
            uint32_t addr = (uint32_t)(key * 128 + ((chunk ^ (key & 7)) * 16) + (h4 & 1) * 8);
            *(uint32_t*)(sK + addr)     = f2h2(kv.x, kv.y);
            *(uint32_t*)(sK + addr + 4) = f2h2(kv.z, kv.w);

            float4 vv = *(const float4*)&g_v[(size_t)(b * TT + s0 + key) * HH + h4 * 4];
            int h0 = h4 * 4;
            __half hv[4] = {__float2half_rn(vv.x), __float2half_rn(vv.y),
                            __float2half_rn(vv.z), __float2half_rn(vv.w)};
#pragma unroll
            for (int j = 0; j < 4; j++) {
                int h = h0 + j;
                uint32_t vaddr = (uint32_t)(h * 128 + (((key >> 3) ^ (h & 7)) * 16) +
                                            (key & 7) * 2);
                *(__half*)(sV + vaddr) = hv[j];
            }
        }
        __syncthreads();

        if (s0 > wmax) continue;

        float s[8][4];
#pragma unroll
        for (int ng = 0; ng < 8; ng++)
#pragma unroll
            for (int j = 0; j < 4; j++) s[ng][j] = 0.f;

#pragma unroll
        for (int kg = 0; kg < 4; kg++) {
            int rowB = kg * 16 + (lane & 7) + ((lane >> 4) << 3);
#pragma unroll
            for (int ks = 0; ks < 4; ks++) {
                int chunk = ((lane >> 3) & 1) + 2 * ks;
                uint32_t addr = sKb + (uint32_t)(rowB * 128 + ((chunk ^ (rowB & 7)) * 16));
                uint32_t bk[4];
                ldsm4(bk, addr);
                mma16816h(s[2 * kg],     aq[ks], bk[0], bk[1]);
                mma16816h(s[2 * kg + 1], aq[ks], bk[2], bk[3]);
            }
        }

        const bool diag = (s0 + 63 >= wmin);
#pragma unroll
        for (int ng = 0; ng < 8; ng++) {
            int scol = s0 + ng * 8 + (lane & 3) * 2;
            if (diag) {
                s[ng][0] = (scol     > t0) ? -1e30f : s[ng][0] * scale;
                s[ng][1] = (scol + 1 > t0) ? -1e30f : s[ng][1] * scale;
                s[ng][2] = (scol     > t1) ? -1e30f : s[ng][2] * scale;
                s[ng][3] = (scol + 1 > t1) ? -1e30f : s[ng][3] * scale;
            } else {
                s[ng][0] *= scale; s[ng][1] *= scale;
                s[ng][2] *= scale; s[ng][3] *= scale;
            }
        }

        float mx0 = -1e30f, mx1 = -1e30f;
#pragma unroll
        for (int ng = 0; ng < 8; ng++) {
            mx0 = fmaxf(mx0, fmaxf(s[ng][0], s[ng][1]));
            mx1 = fmaxf(mx1, fmaxf(s[ng][2], s[ng][3]));
        }
        mx0 = fmaxf(mx0, __shfl_xor_sync(0xffffffffu, mx0, 1));
        mx0 = fmaxf(mx0, __shfl_xor_sync(0xffffffffu, mx0, 2));
        mx1 = fmaxf(mx1, __shfl_xor_sync(0xffffffffu, mx1, 1));
        mx1 = fmaxf(mx1, __shfl_xor_sync(0xffffffffu, mx1, 2));

        float mn0 = fmaxf(m0, mx0);
        float mn1 = fmaxf(m1, mx1);
        float c0 = __expf(m0 - mn0);
        float c1 = __expf(m1 - mn1);

        float sum0 = 0.f, sum1 = 0.f;
#pragma unroll
        for (int ng = 0; ng < 8; ng++) {
            s[ng][0] = __expf(s[ng][0] - mn0);
            s[ng][1] = __expf(s[ng][1] - mn0);
            s[ng][2] = __expf(s[ng][2] - mn1);
            s[ng][3] = __expf(s[ng][3] - mn1);
            sum0 += s[ng][0] + s[ng][1];
            sum1 += s[ng][2] + s[ng][3];
        }
        sum0 += __shfl_xor_sync(0xffffffffu, sum0, 1);
        sum0 += __shfl_xor_sync(0xffffffffu, sum0, 2);
        sum1 += __shfl_xor_sync(0xffffffffu, sum1, 1);
        sum1 += __shfl_xor_sync(0xffffffffu, sum1, 2);

        l0 = l0 * c0 + sum0;
        l1 = l1 * c1 + sum1;
        m0 = mn0; m1 = mn1;

#pragma unroll
        for (int ng = 0; ng < 8; ng++) {
            o[ng][0] *= c0; o[ng][1] *= c0;
            o[ng][2] *= c1; o[ng][3] *= c1;
        }

#pragma unroll
        for (int ks = 0; ks < 4; ks++) {
            uint32_t ap[4];
            ap[0] = f2h2(s[2 * ks][0],     s[2 * ks][1]);
            ap[1] = f2h2(s[2 * ks][2],     s[2 * ks][3]);
            ap[2] = f2h2(s[2 * ks + 1][0], s[2 * ks + 1][1]);
            ap[3] = f2h2(s[2 * ks + 1][2], s[2 * ks + 1][3]);
#pragma unroll
            for (int hg = 0; hg < 4; hg++) {
                int rowV = hg * 16 + (lane & 7) + ((lane >> 4) << 3);
                int chunk = ((lane >> 3) & 1) + 2 * ks;
                uint32_t addr = sVb + (uint32_t)(rowV * 128 + ((chunk ^ (rowV & 7)) * 16));
                uint32_t bv[4];
                ldsm4(bv, addr);
                mma16816h(o[2 * hg],     ap, bv[0], bv[1]);
                mma16816h(o[2 * hg + 1], ap, bv[2], bv[3]);
            }
        }
    }

    const int grow0 = b * TT + t0;
    const int grow1 = b * TT + t1;
    if ((lane & 3) == 0) {
        g_pm[split * BT + grow0] = m0;
        g_pl[split * BT + grow0] = l0;
        g_pm[split * BT + grow1] = m1;
        g_pl[split * BT + grow1] = l1;
    }
    float* po0 = g_po + ((size_t)split * BT + grow0) * HH;
    float* po1 = g_po + ((size_t)split * BT + grow1) * HH;
#pragma unroll
    for (int ng = 0; ng < 8; ng++) {
        int col = ng * 8 + (lane & 3) * 2;
        *(float2*)&po0[col] = make_float2(o[ng][0], o[ng][1]);
        *(float2*)&po1[col] = make_float2(o[ng][2], o[ng][3]);
    }
}

// ---------------------------------------------------------------------------
// Kernel 3: combine partials. 256 threads, 4 rows per block.
// ---------------------------------------------------------------------------
__global__ __launch_bounds__(256) void combine_kernel(float* __restrict__ out)
{
    const int row = blockIdx.x * 4 + (threadIdx.x >> 6);
    const int h = threadIdx.x & 63;

    float mv[NSPLIT], lv[NSPLIT];
#pragma unroll
    for (int i = 0; i < NSPLIT; i++) {
        mv[i] = g_pm[i * BT + row];
        lv[i] = g_pl[i * BT + row];
    }
    float M = mv[0];
#pragma unroll
    for (int i = 1; i < NSPLIT; i++) M = fmaxf(M, mv[i]);

    float L = 0.f, acc = 0.f;
#pragma unroll
    for (int i = 0; i < NSPLIT; i++) {
        float w = __expf(mv[i] - M);
        L += lv[i] * w;
        acc += g_po[((size_t)i * BT + row) * HH + h] * w;
    }
    out[(size_t)row * HH + h] = acc / L;
}

// ---------------------------------------------------------------------------
extern "C" void kernel_launch(void* const* d_in, const int* in_sizes, int n_in,
                              void* d_out, int out_size)
{
    const float* x  = (const float*)d_in[0];
    const float* Wk = (const float*)d_in[1];
    const float* Wq = (const float*)d_in[2];
    const float* Wv = (const float*)d_in[3];
    float* out = (float*)d_out;

    static bool attr_set = false;
    if (!attr_set) {
        cudaFuncSetAttribute(qkv_mma_kernel,
                             cudaFuncAttributeMaxDynamicSharedMemorySize, QKV_SMEM);
        attr_set = true;
    }

    prep_w_kernel<<<3 * HH * CC / 256, 256>>>(Wk, Wq, Wv);
    qkv_mma_kernel<<<BT / 128, 256, QKV_SMEM>>>(x);
    attn_mma_kernel<<<dim3(TT / 128, BB, NSPLIT), 256>>>();
    combine_kernel<<<dim3(BT / 4), 256>>>(out);
}

// round 10
// speedup vs baseline: 4.0588x; 1.1955x over previous
#include <cuda_runtime.h>
#include <cuda_bf16.h>
#include <cuda_fp16.h>
#include <cstdint>

// Problem constants
#define BB 8
#define TT 2048
#define CC 1024
#define HH 64
#define BT (BB * TT)             // 16384 rows
#define NSPLIT 4
#define SPLIT_LEN (TT / NSPLIT)  // 512

// q pre-scale: (1/sqrt(64)) * log2(e)  -> softmax in exp2 domain
#define SCALE_LOG2E 0.18033688011112042f

// Scratch (device globals)
__device__ __align__(16) __half g_qh[BT * HH];  // swizzled 128B rows, q pre-scaled
__device__ __align__(16) __half g_kh[BT * HH];  // swizzled 128B rows
__device__ __align__(16) __half g_vh[BT * HH];  // swizzled 128B rows
__device__ float g_pm[NSPLIT * BT];
__device__ float g_pl[NSPLIT * BT];
__device__ float g_po[NSPLIT * BT * HH];
__device__ __align__(16) __nv_bfloat16 g_whi[3 * HH * CC];
__device__ __align__(16) __nv_bfloat16 g_wlo[3 * HH * CC];

// ---------------------------------------------------------------------------
// helpers
// ---------------------------------------------------------------------------
__device__ __forceinline__ uint32_t smem_u32(const void* p) {
    uint32_t a;
    asm("{ .reg .u64 t; cvta.to.shared.u64 t, %1; cvt.u32.u64 %0, t; }"
        : "=r"(a) : "l"(p));
    return a;
}

__device__ __forceinline__ void ldsm4(uint32_t* r, uint32_t addr) {
    asm volatile("ldmatrix.sync.aligned.m8n8.x4.shared.b16 {%0,%1,%2,%3}, [%4];"
                 : "=r"(r[0]), "=r"(r[1]), "=r"(r[2]), "=r"(r[3]) : "r"(addr));
}

__device__ __forceinline__ void ldsm4t(uint32_t* r, uint32_t addr) {
    asm volatile("ldmatrix.sync.aligned.m8n8.x4.trans.shared.b16 {%0,%1,%2,%3}, [%4];"
                 : "=r"(r[0]), "=r"(r[1]), "=r"(r[2]), "=r"(r[3]) : "r"(addr));
}

__device__ __forceinline__ void mma16816(float* c, const uint32_t* a,
                                         uint32_t b0, uint32_t b1) {
    asm volatile(
        "mma.sync.aligned.m16n8k16.row.col.f32.bf16.bf16.f32 "
        "{%0,%1,%2,%3}, {%4,%5,%6,%7}, {%8,%9}, {%0,%1,%2,%3};"
        : "+f"(c[0]), "+f"(c[1]), "+f"(c[2]), "+f"(c[3])
        : "r"(a[0]), "r"(a[1]), "r"(a[2]), "r"(a[3]), "r"(b0), "r"(b1));
}

__device__ __forceinline__ void mma16816h(float* c, const uint32_t* a,
                                          uint32_t b0, uint32_t b1) {
    asm volatile(
        "mma.sync.aligned.m16n8k16.row.col.f32.f16.f16.f32 "
        "{%0,%1,%2,%3}, {%4,%5,%6,%7}, {%8,%9}, {%0,%1,%2,%3};"
        : "+f"(c[0]), "+f"(c[1]), "+f"(c[2]), "+f"(c[3])
        : "r"(a[0]), "r"(a[1]), "r"(a[2]), "r"(a[3]), "r"(b0), "r"(b1));
}

__device__ __forceinline__ uint32_t f2h2(float a, float b) {
    __half2 h = __floats2half2_rn(a, b);
    return *(uint32_t*)&h;
}

__device__ __forceinline__ void cp16(uint32_t dst, const void* src) {
    asm volatile("cp.async.ca.shared.global [%0], [%1], 16;"
                 :: "r"(dst), "l"(src) : "memory");
}
#define CP_COMMIT() asm volatile("cp.async.commit_group;" ::: "memory")
#define CP_WAIT(n)  asm volatile("cp.async.wait_group %0;" :: "n"(n) : "memory")

// ---------------------------------------------------------------------------
// Kernel 0: split W into bf16 hi/lo, transposed to [w][n][k]
// ---------------------------------------------------------------------------
__global__ __launch_bounds__(256) void prep_w_kernel(
    const float* __restrict__ Wk, const float* __restrict__ Wq,
    const float* __restrict__ Wv)
{
    int i = blockIdx.x * 256 + threadIdx.x;
    int w = i >> 16;
    int rem = i & 65535;
    int n = rem >> 10;
    int k = rem & 1023;
    const float* W = (w == 0) ? Wk : (w == 1) ? Wq : Wv;
    float v = W[k * HH + n];
    __nv_bfloat16 h = __float2bfloat16(v);
    float r = v - __bfloat162float(h);
    g_whi[i] = h;
    g_wlo[i] = __float2bfloat16(r);
}

// ---------------------------------------------------------------------------
// Kernel 1: QKV via mma.sync (bf16 split precision). Single-barrier pipeline.
// Outputs fp16, swizzled 128B rows; q pre-scaled by SCALE_LOG2E.
// ---------------------------------------------------------------------------
#define KC2 64
#define NCHUNK2 (CC / KC2)      // 16
#define QA_HI 0
#define QA_LO 16384
#define QB_HI 32768             // + w*8192
#define QB_LO 57344             // + w*8192
#define QSTAGE 81920
#define QKV_SMEM (2 * QSTAGE)   // 160 KB

__global__ __launch_bounds__(256, 1) void qkv_mma_kernel(const float* __restrict__ x)
{
    extern __shared__ __align__(128) char sm[];
    const uint32_t sbase = smem_u32(sm);

    const int tid = threadIdx.x;
    const int wid = tid >> 5;
    const int lane = tid & 31;
    const int m0 = blockIdx.x * 128;

    float acc[3][8][4];
#pragma unroll
    for (int w = 0; w < 3; w++)
#pragma unroll
        for (int nt = 0; nt < 8; nt++)
#pragma unroll
            for (int j = 0; j < 4; j++) acc[w][nt][j] = 0.f;

    float4 xr[8];

    auto issue_b = [&](int k0, uint32_t stb) {
#pragma unroll
        for (int it = 0; it < 6; it++) {
            int g = tid + it * 256;
            int w = g >> 9;
            int n = (g >> 3) & 63;
            int ch = g & 7;
            uint32_t dst = stb + (uint32_t)(w * 8192 + n * 128 + ((ch ^ (n & 7)) * 16));
            const __nv_bfloat16* srch = g_whi + (size_t)w * (HH * CC) + n * CC + k0 + ch * 8;
            const __nv_bfloat16* srcl = g_wlo + (size_t)w * (HH * CC) + n * CC + k0 + ch * 8;
            cp16(QB_HI + dst, srch);
            cp16(QB_LO + dst, srcl);
        }
        CP_COMMIT();
    };

    auto load_a = [&](int k0) {
#pragma unroll
        for (int it = 0; it < 8; it++) {
            int f = tid + it * 256;
            int row = f >> 4, q4 = f & 15;
            xr[it] = *(const float4*)&x[(size_t)(m0 + row) * CC + k0 + q4 * 4];
        }
    };

    load_a(0);
    issue_b(0, sbase);

    for (int c = 0; c < NCHUNK2; c++) {
        const int buf = c & 1;
        char* st = sm + buf * QSTAGE;
        const uint32_t stb = sbase + buf * QSTAGE;

        // ---- A regs -> smem (fp32 -> bf16 hi/lo, swizzled) ----
#pragma unroll
        for (int it = 0; it < 8; it++) {
            int f = tid + it * 256;
            int row = f >> 4, q4 = f & 15;
            float4 v = xr[it];
            __nv_bfloat16 h0 = __float2bfloat16(v.x);
            __nv_bfloat16 h1 = __float2bfloat16(v.y);
            __nv_bfloat16 h2 = __float2bfloat16(v.z);
            __nv_bfloat16 h3 = __float2bfloat16(v.w);
            __nv_bfloat16 l0 = __float2bfloat16(v.x - __bfloat162float(h0));
            __nv_bfloat16 l1 = __float2bfloat16(v.y - __bfloat162float(h1));
            __nv_bfloat16 l2 = __float2bfloat16(v.z - __bfloat162float(h2));
            __nv_bfloat16 l3 = __float2bfloat16(v.w - __bfloat162float(h3));
            uint2 hp = make_uint2(
                (uint32_t)__bfloat16_as_ushort(h0) | ((uint32_t)__bfloat16_as_ushort(h1) << 16),
                (uint32_t)__bfloat16_as_ushort(h2) | ((uint32_t)__bfloat16_as_ushort(h3) << 16));
            uint2 lp = make_uint2(
                (uint32_t)__bfloat16_as_ushort(l0) | ((uint32_t)__bfloat16_as_ushort(l1) << 16),
                (uint32_t)__bfloat16_as_ushort(l2) | ((uint32_t)__bfloat16_as_ushort(l3) << 16));
            int ch = q4 >> 1;
            uint32_t off = (uint32_t)(row * 128 + ((ch ^ (row & 7)) * 16) + (q4 & 1) * 8);
            *(uint2*)(st + QA_HI + off) = hp;
            *(uint2*)(st + QA_LO + off) = lp;
        }

        if (c + 1 < NCHUNK2) load_a((c + 1) * KC2);
        CP_WAIT(0);
        __syncthreads();
        // All warps past this sync => mma(c-1) complete => safe to overwrite
        // buf (c+1)&1 == (c-1)&1 via cp.async now.
        if (c + 1 < NCHUNK2) issue_b((c + 1) * KC2, sbase + ((c + 1) & 1) * QSTAGE);

        // ---- MMA on buffer c&1 ----
        const int arow = wid * 16 + (lane & 15);
        const int browbase = (lane & 7) + ((lane >> 4) << 3);
        const int bchlo = (lane >> 3) & 1;
#pragma unroll
        for (int ks = 0; ks < 4; ks++) {
            uint32_t ah[4], al[4];
            {
                int ch = 2 * ks + (lane >> 4);
                uint32_t addr = stb + (uint32_t)(arow * 128 + ((ch ^ (arow & 7)) * 16));
                ldsm4(ah, QA_HI + addr);
                ldsm4(al, QA_LO + addr);
            }
#pragma unroll
            for (int w = 0; w < 3; w++) {
#pragma unroll
                for (int ng = 0; ng < 4; ng++) {
                    int rowB = ng * 16 + browbase;
                    int ch = bchlo + 2 * ks;
                    uint32_t addr = stb + (uint32_t)(w * 8192 + rowB * 128 +
                                                     ((ch ^ (rowB & 7)) * 16));
                    uint32_t bh[4], bl[4];
                    ldsm4(bh, QB_HI + addr);
                    ldsm4(bl, QB_LO + addr);
                    mma16816(acc[w][2 * ng],     ah, bh[0], bh[1]);
                    mma16816(acc[w][2 * ng],     ah, bl[0], bl[1]);
                    mma16816(acc[w][2 * ng],     al, bh[0], bh[1]);
                    mma16816(acc[w][2 * ng + 1], ah, bh[2], bh[3]);
                    mma16816(acc[w][2 * ng + 1], ah, bl[2], bl[3]);
                    mma16816(acc[w][2 * ng + 1], al, bh[2], bh[3]);
                }
            }
        }
    }

    // ---- epilogue: fp16, swizzled rows; q scaled ----
    char* outs[3] = {(char*)g_kh, (char*)g_qh, (char*)g_vh};
    const float muls[3] = {1.f, SCALE_LOG2E, 1.f};
    const int r0 = m0 + wid * 16 + (lane >> 2);
    const int r1 = r0 + 8;
    const uint32_t inner = (lane & 3) * 4;
#pragma unroll
    for (int w = 0; w < 3; w++) {
        char* op = outs[w];
        float mu = muls[w];
#pragma unroll
        for (int nt = 0; nt < 8; nt++) {
            uint32_t a0 = f2h2(acc[w][nt][0] * mu, acc[w][nt][1] * mu);
            uint32_t a1 = f2h2(acc[w][nt][2] * mu, acc[w][nt][3] * mu);
            *(uint32_t*)(op + (size_t)r0 * 128 + ((nt ^ (r0 & 7)) * 16) + inner) = a0;
            *(uint32_t*)(op + (size_t)r1 * 128 + ((nt ^ (r1 & 7)) * 16) + inner) = a1;
        }
    }
}

// ---------------------------------------------------------------------------
// Kernel 2: FA-2 flash attention, fp16 mma, causal, split-K.
// Direct cp.async staging of pre-swizzled fp16 tiles; double-buffered K/V;
// V^T operand via ldmatrix.trans; exp2 domain (scale folded into q).
// ---------------------------------------------------------------------------
__global__ __launch_bounds__(256, 2) void attn_mma_kernel()
{
    __shared__ __align__(128) char sQ[16384];
    __shared__ __align__(128) char sKV[2][16384];   // [stage]: K at 0, V at 8192

    const int qtile = blockIdx.x;
    const int b = blockIdx.y;
    const int split = blockIdx.z;
    const int tid = threadIdx.x;
    const int wid = tid >> 5;
    const int lane = tid & 31;

    const int qrow0 = qtile * 128;
    const int ks0 = split * SPLIT_LEN;
    if (ks0 >= qrow0 + 128) return;                 // no causal work for this CTA
    const int ks1 = min(ks0 + SPLIT_LEN, qrow0 + 128);
    const int ntile = (ks1 - ks0) >> 6;             // 64-key tiles, >= 1

    const uint32_t sQb = smem_u32(sQ);
    const uint32_t sKVb = smem_u32(sKV);

    // ---- prologue: stage Q + first KV tile (one cp.async group) ----
    {
        const char* srcQ = (const char*)g_qh + (size_t)(b * TT + qrow0) * 128;
#pragma unroll
        for (int i = 0; i < 4; i++) {               // 1024 chunks of 16B
            int f = tid + i * 256;
            cp16(sQb + f * 16, srcQ + f * 16);
        }
        const char* srcK = (const char*)g_kh + (size_t)(b * TT + ks0) * 128;
        const char* srcV = (const char*)g_vh + (size_t)(b * TT + ks0) * 128;
#pragma unroll
        for (int i = 0; i < 2; i++) {               // 512 chunks each
            int f = tid + i * 256;
            cp16(sKVb + f * 16, srcK + f * 16);
            cp16(sKVb + 8192 + f * 16, srcV + f * 16);
        }
        CP_COMMIT();
    }

    float o[8][4];
#pragma unroll
    for (int ng = 0; ng < 8; ng++)
#pragma unroll
        for (int j = 0; j < 4; j++) o[ng][j] = 0.f;
    float m0 = -1e30f, m1 = -1e30f, l0 = 0.f, l1 = 0.f;

    const int t0 = qrow0 + wid * 16 + (lane >> 2);
    const int t1 = t0 + 8;
    const int wmin = qrow0 + wid * 16;
    const int wmax = wmin + 15;

    uint32_t aq[4][4];
    bool qloaded = false;

    const int vkeybase = ((lane >> 3) & 1) * 8 + (lane & 7);
    const int vchsel = lane >> 4;

    for (int it = 0; it < ntile; it++) {
        const int s0 = ks0 + it * 64;
        const uint32_t stg = sKVb + (uint32_t)((it & 1) * 16384);

        CP_WAIT(0);
        __syncthreads();

        // stage next tile into other buffer (prev readers done via sync)
        if (it + 1 < ntile) {
            const int sn = s0 + 64;
            const char* srcK = (const char*)g_kh + (size_t)(b * TT + sn) * 128;
            const char* srcV = (const char*)g_vh + (size_t)(b * TT + sn) * 128;
            uint32_t dst = sKVb + (uint32_t)(((it + 1) & 1) * 16384);
#pragma unroll
            for (int i = 0; i < 2; i++) {
                int f = tid + i * 256;
                cp16(dst + f * 16, srcK + f * 16);
                cp16(dst + 8192 + f * 16, srcV + f * 16);
            }
            CP_COMMIT();
        }

        if (!qloaded) {
            int row = wid * 16 + (lane & 15);
#pragma unroll
            for (int ks = 0; ks < 4; ks++) {
                int chunk = 2 * ks + (lane >> 4);
                ldsm4(aq[ks], sQb + (uint32_t)(row * 128 + ((chunk ^ (row & 7)) * 16)));
            }
            qloaded = true;
        }

        if (s0 > wmax) continue;                    // tile above this warp's rows

        // ---- S = Q K^T (scores already in exp2 domain via q pre-scale) ----
        float s[8][4];
#pragma unroll
        for (int ng = 0; ng < 8; ng++)
#pragma unroll
            for (int j = 0; j < 4; j++) s[ng][j] = 0.f;

#pragma unroll
        for (int kg = 0; kg < 4; kg++) {
            int rowB = kg * 16 + (lane & 7) + ((lane >> 4) << 3);
#pragma unroll
            for (int ks = 0; ks < 4; ks++) {
                int chunk = ((lane >> 3) & 1) + 2 * ks;
                uint32_t addr = stg + (uint32_t)(rowB * 128 + ((chunk ^ (rowB & 7)) * 16));
                uint32_t bk[4];
                ldsm4(bk, addr);
                mma16816h(s[2 * kg],     aq[ks], bk[0], bk[1]);
                mma16816h(s[2 * kg + 1], aq[ks], bk[2], bk[3]);
            }
        }

        // ---- causal mask ----
        if (s0 + 63 >= wmin) {
#pragma unroll
            for (int ng = 0; ng < 8; ng++) {
                int scol = s0 + ng * 8 + (lane & 3) * 2;
                if (scol     > t0) s[ng][0] = -1e30f;
                if (scol + 1 > t0) s[ng][1] = -1e30f;
                if (scol     > t1) s[ng][2] = -1e30f;
                if (scol + 1 > t1) s[ng][3] = -1e30f;
            }
        }

        // ---- online softmax (exp2) ----
        float mx0 = -1e30f, mx1 = -1e30f;
#pragma unroll
        for (int ng = 0; ng < 8; ng++) {
            mx0 = fmaxf(mx0, fmaxf(s[ng][0], s[ng][1]));
            mx1 = fmaxf(mx1, fmaxf(s[ng][2], s[ng][3]));
        }
        mx0 = fmaxf(mx0, __shfl_xor_sync(0xffffffffu, mx0, 1));
        mx0 = fmaxf(mx0, __shfl_xor_sync(0xffffffffu, mx0, 2));
        mx1 = fmaxf(mx1, __shfl_xor_sync(0xffffffffu, mx1, 1));
        mx1 = fmaxf(mx1, __shfl_xor_sync(0xffffffffu, mx1, 2));

        float mn0 = fmaxf(m0, mx0);
        float mn1 = fmaxf(m1, mx1);
        float c0 = exp2f(m0 - mn0);
        float c1 = exp2f(m1 - mn1);

        float sum0 = 0.f, sum1 = 0.f;
#pragma unroll
        for (int ng = 0; ng < 8; ng++) {
            s[ng][0] = exp2f(s[ng][0] - mn0);
            s[ng][1] = exp2f(s[ng][1] - mn0);
            s[ng][2] = exp2f(s[ng][2] - mn1);
            s[ng][3] = exp2f(s[ng][3] - mn1);
            sum0 += s[ng][0] + s[ng][1];
            sum1 += s[ng][2] + s[ng][3];
        }
        sum0 += __shfl_xor_sync(0xffffffffu, sum0, 1);
        sum0 += __shfl_xor_sync(0xffffffffu, sum0, 2);
        sum1 += __shfl_xor_sync(0xffffffffu, sum1, 1);
        sum1 += __shfl_xor_sync(0xffffffffu, sum1, 2);

        l0 = l0 * c0 + sum0;
        l1 = l1 * c1 + sum1;
        m0 = mn0; m1 = mn1;

#pragma unroll
        for (int ng = 0; ng < 8; ng++) {
            o[ng][0] *= c0; o[ng][1] *= c0;
            o[ng][2] *= c1; o[ng][3] *= c1;
        }

        // ---- O += P V  (V from [key][h] rows via ldmatrix.trans) ----
        const uint32_t sVstg = stg + 8192;
#pragma unroll
        for (int ks = 0; ks < 4; ks++) {
            uint32_t ap[4];
            ap[0] = f2h2(s[2 * ks][0],     s[2 * ks][1]);
            ap[1] = f2h2(s[2 * ks][2],     s[2 * ks][3]);
            ap[2] = f2h2(s[2 * ks + 1][0], s[2 * ks + 1][1]);
            ap[3] = f2h2(s[2 * ks + 1][2], s[2 * ks + 1][3]);
            int keyl = ks * 16 + vkeybase;
#pragma unroll
            for (int hg = 0; hg < 4; hg++) {
                int ch = hg * 2 + vchsel;
                uint32_t addr = sVstg + (uint32_t)(keyl * 128 + ((ch ^ (keyl & 7)) * 16));
                uint32_t bv[4];
                ldsm4t(bv, addr);
                mma16816h(o[2 * hg],     ap, bv[0], bv[1]);
                mma16816h(o[2 * hg + 1], ap, bv[2], bv[3]);
            }
        }
    }

    // ---- write partials ----
    const int grow0 = b * TT + t0;
    const int grow1 = b * TT + t1;
    if ((lane & 3) == 0) {
        g_pm[split * BT + grow0] = m0;
        g_pl[split * BT + grow0] = l0;
        g_pm[split * BT + grow1] = m1;
        g_pl[split * BT + grow1] = l1;
    }
    float* po0 = g_po + ((size_t)split * BT + grow0) * HH;
    float* po1 = g_po + ((size_t)split * BT + grow1) * HH;
#pragma unroll
    for (int ng = 0; ng < 8; ng++) {
        int col = ng * 8 + (lane & 3) * 2;
        *(float2*)&po0[col] = make_float2(o[ng][0], o[ng][1]);
        *(float2*)&po1[col] = make_float2(o[ng][2], o[ng][3]);
    }
}

// ---------------------------------------------------------------------------
// Kernel 3: combine partials (active splits only; exp2 domain).
// ---------------------------------------------------------------------------
__global__ __launch_bounds__(256) void combine_kernel(float* __restrict__ out)
{
    const int row = blockIdx.x * 4 + (threadIdx.x >> 6);
    const int h = threadIdx.x & 63;
    const int t = row & (TT - 1);
    const int nact = (t >> 9) + 1;   // splits with ks0 <= t

    float M = -1e30f;
    float mv[NSPLIT], lv[NSPLIT];
    for (int i = 0; i < nact; i++) {
        mv[i] = g_pm[i * BT + row];
        lv[i] = g_pl[i * BT + row];
        M = fmaxf(M, mv[i]);
    }

    float L = 0.f, acc = 0.f;
    for (int i = 0; i < nact; i++) {
        float w = exp2f(mv[i] - M);
        L += lv[i] * w;
        acc += g_po[((size_t)i * BT + row) * HH + h] * w;
    }
    out[(size_t)row * HH + h] = acc / L;
}

// ---------------------------------------------------------------------------
extern "C" void kernel_launch(void* const* d_in, const int* in_sizes, int n_in,
                              void* d_out, int out_size)
{
    const float* x  = (const float*)d_in[0];
    const float* Wk = (const float*)d_in[1];
    const float* Wq = (const float*)d_in[2];
    const float* Wv = (const float*)d_in[3];
    float* out = (float*)d_out;

    static bool attr_set = false;
    if (!attr_set) {
        cudaFuncSetAttribute(qkv_mma_kernel,
                             cudaFuncAttributeMaxDynamicSharedMemorySize, QKV_SMEM);
        attr_set = true;
    }

    prep_w_kernel<<<3 * HH * CC / 256, 256>>>(Wk, Wq, Wv);
    qkv_mma_kernel<<<BT / 128, 256, QKV_SMEM>>>(x);
    attn_mma_kernel<<<dim3(TT / 128, BB, NSPLIT), 256>>>();
    combine_kernel<<<dim3(BT / 4), 256>>>(out);
}